// round 15
// baseline (speedup 1.0000x reference)
#include <cuda_runtime.h>
#include <cuda_bf16.h>
#include <cstddef>
#include <cstdint>

// LIF recurrence: v = alpha*v + beta*c; s = (v >= 1); v = s ? 0 : v
// float2 per thread (2 neurons). Per-warp private smem ring via cp.async.cg.
// R13 -> R14: CHUNK 32->64 via 96KB DYNAMIC shared memory (static limit is
// 48KB). The only lever that has moved DRAM% proportionally is unidirectional
// burst length (R/W turnaround at the memory controller); this doubles it
// again: 16KB read bursts / 32KB write bursts per warp. SLOTS=3, AHEAD=2,
// same per-warp-private structure and tail drain as the passing R12/R13.
// Output layout: out[0 : T*N] = spikes, out[T*N : 2*T*N] = voltages.

#define T_STEPS 2048
#define N_NEUR  32768
#define N2      (N_NEUR / 2)       // float2 elements per step = 16384
#define N4      (N_NEUR / 4)       // float4 elements per step = 8192
#define BLOCK   64                 // 2 warps; grid = 256
#define CHUNK   64                 // steps per cp.async group (16KB/warp reads)
#define NCHUNKS (T_STEPS / CHUNK)  // 32
#define SLOTS   3                  // ring depth in chunks (per warp)
#define AHEAD   2                  // chunk-groups in flight per warp

// ring: 2 warps * SLOTS * CHUNK * 32 lanes * 8B = 98304 B (96KB dynamic)
#define RING_BYTES (2 * SLOTS * CHUNK * 32 * 8)

__device__ __forceinline__ void lif_step2(float2& v, float2 c, float2& s_out, float2& v_out) {
    const float alpha = (float)0.951229424500714;   // exp(-0.05), double -> f32
    const float beta  = (float)0.048770575499286;   // 1 - exp(-0.05), double -> f32
    v.x = alpha * v.x + beta * c.x;                 // FFMA
    v.y = alpha * v.y + beta * c.y;
    const bool fx = (v.x >= 1.0f);
    const bool fy = (v.y >= 1.0f);
    s_out.x = fx ? 1.0f : 0.0f;
    s_out.y = fy ? 1.0f : 0.0f;
    v.x = fx ? 0.0f : v.x;                          // V_RESET = 0
    v.y = fy ? 0.0f : v.y;
    v_out = v;
}

__device__ __forceinline__ void cp_async16(uint32_t smem_addr, const void* gmem_ptr) {
    asm volatile("cp.async.cg.shared.global [%0], [%1], 16;\n"
                 :: "r"(smem_addr), "l"(gmem_ptr) : "memory");
}
__device__ __forceinline__ void cp_commit() {
    asm volatile("cp.async.commit_group;\n" ::: "memory");
}
template <int N>
__device__ __forceinline__ void cp_wait() {
    asm volatile("cp.async.wait_group %0;\n" :: "n"(N) : "memory");
}

__global__ void __launch_bounds__(BLOCK, 2)
lif_kernel(const float4* __restrict__ cur4,   // currents viewed as float4
           const float2* __restrict__ v0,
           float2* __restrict__ out)
{
    extern __shared__ float2 ring[];          // [2][SLOTS][CHUNK][32]

    const int tid  = threadIdx.x;
    const int wid  = tid >> 5;
    const int lane = tid & 31;
    const int n    = blockIdx.x * BLOCK + tid;        // float2 lane, 0..N2-1

    float2 v = v0[n];

    float2* sp = out + n;                                  // spikes base
    float2* vp = out + n + (size_t)T_STEPS * (size_t)N2;   // voltages base

    // Producer mapping (per warp, 256B row per step = 16 float4):
    // lane = jj*16 + ii : ii = float4 index in row, jj = step parity.
    // Lane handles steps u = 2*u2 + jj, u2 = 0..CHUNK/2-1.
    const int ii = lane & 15;
    const int jj = lane >> 4;
    const float4* gsrc = cur4 + (size_t)blockIdx.x * 32 + (size_t)(wid * 16 + ii);

    const uint32_t ring_base = (uint32_t)__cvta_generic_to_shared(ring);

    auto issue_chunk = [&](int c) {
        const int slot = c % SLOTS;
        const uint32_t row0 = (uint32_t)(((wid * SLOTS + slot) * CHUNK) * 32 + ii * 2) * 8u;
        #pragma unroll
        for (int u2 = 0; u2 < CHUNK / 2; ++u2) {
            const int u = 2 * u2 + jj;
            const int t = c * CHUNK + u;
            const uint32_t dst = ring_base + row0 + (uint32_t)u * 256u;
            cp_async16(dst, gsrc + (size_t)t * N4);
        }
        cp_commit();
    };

    // Prologue: AHEAD chunks in flight (per warp).
    #pragma unroll
    for (int c = 0; c < AHEAD; ++c)
        issue_chunk(c);

    for (int c = 0; c < NCHUNKS; ++c) {
        // Steady state: AHEAD groups pending -> wait<AHEAD-1> drains chunk c.
        // Tail (no more issues): fewer pending -> wait<AHEAD-1> would be a
        // NO-OP; drain everything with wait<0> instead.
        if (c + AHEAD < NCHUNKS)
            cp_wait<AHEAD - 1>();
        else
            cp_wait<0>();
        __syncwarp();             // cross-lane visibility within the warp

        const int slot = c % SLOTS;
        const float2* rbase = ring + ((size_t)(wid * SLOTS + slot) * CHUNK) * 32 + lane;

        // Consume chunk c: 64 steps (reads only this warp's ring region).
        #pragma unroll
        for (int u = 0; u < CHUNK; ++u) {
            const int t = c * CHUNK + u;
            float2 cc = rbase[u * 32];
            float2 s, vo;
            lif_step2(v, cc, s, vo);
            const size_t off = (size_t)t * N2;
            __stcs(sp + off, s);
            __stcs(vp + off, vo);
        }

        // Refill: chunk c+AHEAD -> slot (c+2)%3 == (c-1)%3, which this warp
        // finished reading at iteration c-1 (warp program order -> safe WAR).
        if (c + AHEAD < NCHUNKS)
            issue_chunk(c + AHEAD);
    }
}

extern "C" void kernel_launch(void* const* d_in, const int* in_sizes, int n_in,
                              void* d_out, int out_size)
{
    const float4* currents = (const float4*)d_in[0];   // (T, N) fp32 as float4
    const float2* v0       = (const float2*)d_in[1];   // (N,) fp32 as float2
    float2* out            = (float2*)d_out;           // 2*T*N fp32: [spikes; voltages]

    (void)in_sizes; (void)n_in; (void)out_size;

    // 96KB dynamic smem requires explicit opt-in (host attribute set; not a
    // stream op, not an allocation -> graph-capture legal, idempotent).
    static bool attr_set = false;
    if (!attr_set) {
        cudaFuncSetAttribute(lif_kernel,
                             cudaFuncAttributeMaxDynamicSharedMemorySize,
                             RING_BYTES);
        attr_set = true;
    }

    lif_kernel<<<N2 / BLOCK, BLOCK, RING_BYTES>>>(currents, v0, out);
}

// round 16
// speedup vs baseline: 1.0052x; 1.0052x over previous
#include <cuda_runtime.h>
#include <cuda_bf16.h>
#include <cstddef>
#include <cstdint>

// LIF recurrence: v = alpha*v + beta*c; s = (v >= 1); v = s ? 0 : v
// float2 per thread (2 neurons). Per-warp private 24KB smem ring, cp.async.cg.
// R16 = R13 (best: CHUNK=32, SLOTS=3, static 48KB) + two micro-levers:
//  1) AHEAD 2->3: use the previously idle third ring slot so 2 chunk-groups
//     (16KB) stay in flight during every consume phase (same-warp program
//     order makes the slot reuse WAR-safe). Graded tail drain.
//  2) cp.async L2::256B prefetch hint: each warp-step row is a 256B-aligned
//     fully-consumed span -> fetch as full 256B sectors for better DRAM
//     read burst efficiency, no overfetch.
// Output layout: out[0 : T*N] = spikes, out[T*N : 2*T*N] = voltages.

#define T_STEPS 2048
#define N_NEUR  32768
#define N2      (N_NEUR / 2)       // float2 elements per step = 16384
#define N4      (N_NEUR / 4)       // float4 elements per step = 8192
#define BLOCK   64                 // 2 warps; grid = 256
#define CHUNK   32                 // steps per cp.async group (8KB/warp reads)
#define NCHUNKS (T_STEPS / CHUNK)  // 64
#define SLOTS   3                  // ring depth in chunks (per warp)
#define AHEAD   3                  // chunk-groups in flight per warp

__device__ __forceinline__ void lif_step2(float2& v, float2 c, float2& s_out, float2& v_out) {
    const float alpha = (float)0.951229424500714;   // exp(-0.05), double -> f32
    const float beta  = (float)0.048770575499286;   // 1 - exp(-0.05), double -> f32
    v.x = alpha * v.x + beta * c.x;                 // FFMA
    v.y = alpha * v.y + beta * c.y;
    const bool fx = (v.x >= 1.0f);
    const bool fy = (v.y >= 1.0f);
    s_out.x = fx ? 1.0f : 0.0f;
    s_out.y = fy ? 1.0f : 0.0f;
    v.x = fx ? 0.0f : v.x;                          // V_RESET = 0
    v.y = fy ? 0.0f : v.y;
    v_out = v;
}

__device__ __forceinline__ void cp_async16(uint32_t smem_addr, const void* gmem_ptr) {
    asm volatile("cp.async.cg.shared.global.L2::256B [%0], [%1], 16;\n"
                 :: "r"(smem_addr), "l"(gmem_ptr) : "memory");
}
__device__ __forceinline__ void cp_commit() {
    asm volatile("cp.async.commit_group;\n" ::: "memory");
}
template <int N>
__device__ __forceinline__ void cp_wait() {
    asm volatile("cp.async.wait_group %0;\n" :: "n"(N) : "memory");
}

__global__ void __launch_bounds__(BLOCK, 4)
lif_kernel(const float4* __restrict__ cur4,   // currents viewed as float4
           const float2* __restrict__ v0,
           float2* __restrict__ out)
{
    // ring[warp][slot][step-in-chunk][lane] : 2*3*32*32*8 = 49152 B (48KB)
    __shared__ float2 ring[2][SLOTS][CHUNK][32];

    const int tid  = threadIdx.x;
    const int wid  = tid >> 5;
    const int lane = tid & 31;
    const int n    = blockIdx.x * BLOCK + tid;        // float2 lane, 0..N2-1

    float2 v = v0[n];

    float2* sp = out + n;                                  // spikes base
    float2* vp = out + n + (size_t)T_STEPS * (size_t)N2;   // voltages base

    // Producer mapping (per warp, 256B row per step = 16 float4):
    // lane = jj*16 + ii : ii = float4 index in row, jj = step parity.
    // Lane handles steps u = 2*u2 + jj, u2 = 0..CHUNK/2-1.
    const int ii = lane & 15;
    const int jj = lane >> 4;
    const float4* gsrc = cur4 + (size_t)blockIdx.x * 32 + (size_t)(wid * 16 + ii);

    const uint32_t ring_base = (uint32_t)__cvta_generic_to_shared(ring);

    auto issue_chunk = [&](int c) {
        const int slot = c % SLOTS;
        const uint32_t row0 = (uint32_t)(((wid * SLOTS + slot) * CHUNK) * 32 + ii * 2) * 8u;
        #pragma unroll
        for (int u2 = 0; u2 < CHUNK / 2; ++u2) {
            const int u = 2 * u2 + jj;
            const int t = c * CHUNK + u;
            const uint32_t dst = ring_base + row0 + (uint32_t)u * 256u;
            cp_async16(dst, gsrc + (size_t)t * N4);
        }
        cp_commit();
    };

    // Prologue: AHEAD chunks in flight (per warp).
    #pragma unroll
    for (int c = 0; c < AHEAD; ++c)
        issue_chunk(c);

    for (int c = 0; c < NCHUNKS; ++c) {
        // Pending groups at iter c = min(AHEAD, NCHUNKS - c); to drain chunk
        // c we need wait<pending-1>. Steady state: wait<AHEAD-1>; graded in
        // the tail so the wait never degenerates into a no-op (R9 bug class).
        if (c + AHEAD <= NCHUNKS)
            cp_wait<AHEAD - 1>();
        else if (c + 2 == NCHUNKS)
            cp_wait<1>();
        else
            cp_wait<0>();
        __syncwarp();             // cross-lane visibility within the warp

        const int slot = c % SLOTS;

        // Consume chunk c: 32 steps (reads only this warp's ring region).
        #pragma unroll
        for (int u = 0; u < CHUNK; ++u) {
            const int t = c * CHUNK + u;
            float2 cc = ring[wid][slot][u][lane];
            float2 s, vo;
            lif_step2(v, cc, s, vo);
            const size_t off = (size_t)t * N2;
            __stcs(sp + off, s);
            __stcs(vp + off, vo);
        }

        // Refill: chunk c+AHEAD -> slot (c+3)%3 == c%3, the slot this warp
        // just finished consuming (warp program order -> safe WAR).
        if (c + AHEAD < NCHUNKS)
            issue_chunk(c + AHEAD);
    }
}

extern "C" void kernel_launch(void* const* d_in, const int* in_sizes, int n_in,
                              void* d_out, int out_size)
{
    const float4* currents = (const float4*)d_in[0];   // (T, N) fp32 as float4
    const float2* v0       = (const float2*)d_in[1];   // (N,) fp32 as float2
    float2* out            = (float2*)d_out;           // 2*T*N fp32: [spikes; voltages]

    (void)in_sizes; (void)n_in; (void)out_size;

    lif_kernel<<<N2 / BLOCK, BLOCK>>>(currents, v0, out);
}